// round 8
// baseline (speedup 1.0000x reference)
#include <cuda_runtime.h>
#include <math.h>

#define NMAX 100000
#define EMAX 1600000
#define DH   128

// ---------------- static device scratch (no allocation allowed) ----------------
__device__ int   g_deg[NMAX];          // source-degree (+1 self loop) for norm
__device__ int   g_cnt[NMAX];          // dst-degree (edges only) for CSR
__device__ int   g_start[NMAX];        // CSR row start (exclusive prefix of cnt)
__device__ int   g_wp[NMAX];           // scatter write pointers
__device__ float g_dis[NMAX];          // deg^{-1/2}
__device__ int   g_adj[EMAX];          // CSR adjacency (source ids, grouped by dst)
__device__ float g_h[(size_t)NMAX * DH]; // per-layer linear output h = A @ W
__device__ int   g_bsum[256];
__device__ int   g_boff[256];

// ---------------- preprocessing ----------------
__global__ void init_kernel(int n) {
    int i = blockIdx.x * blockDim.x + threadIdx.x;
    if (i < n) { g_deg[i] = 1; g_cnt[i] = 0; }   // +1 = self loop
}

__global__ void hist_kernel(const int* __restrict__ ei, int E) {
    int e = blockIdx.x * blockDim.x + threadIdx.x;
    if (e < E) {
        int dst = __ldg(ei + e);        // edge_index[0] = row = destination
        int src = __ldg(ei + E + e);    // edge_index[1] = col = source
        atomicAdd(&g_deg[src], 1);
        atomicAdd(&g_cnt[dst], 1);
    }
}

// block-wide scan, 1024 elements per block. pass=0: cnt -> start (+bsum).
// pass=1: bsum -> boff (single block).
__global__ void scan_kernel(int n, int pass) {
    __shared__ int ws[32];
    const int* in = pass ? g_bsum : g_cnt;
    int*      out = pass ? g_boff : g_start;
    int tid = threadIdx.x, lane = tid & 31, wid = tid >> 5;
    int gid = blockIdx.x * 1024 + tid;
    int v = (gid < n) ? in[gid] : 0;
    int x = v;
#pragma unroll
    for (int d = 1; d < 32; d <<= 1) {
        int y = __shfl_up_sync(0xffffffffu, x, d);
        if (lane >= d) x += y;
    }
    if (lane == 31) ws[wid] = x;
    __syncthreads();
    if (wid == 0) {
        int s = ws[lane];
#pragma unroll
        for (int d = 1; d < 32; d <<= 1) {
            int y = __shfl_up_sync(0xffffffffu, s, d);
            if (lane >= d) s += y;
        }
        ws[lane] = s;
    }
    __syncthreads();
    int woff = wid ? ws[wid - 1] : 0;
    if (gid < n) out[gid] = x + woff - v;          // exclusive
    if (pass == 0 && tid == 1023) g_bsum[blockIdx.x] = x + woff; // block total
}

// finalize CSR starts + write pointers, and compute dis = deg^{-1/2} (fused)
__global__ void addoff_kernel(int n) {
    int i = blockIdx.x * blockDim.x + threadIdx.x;
    if (i < n) {
        int s = g_start[i] + g_boff[i >> 10];
        g_start[i] = s;
        g_wp[i] = s;
        g_dis[i] = rsqrtf((float)g_deg[i]);
    }
}

__global__ void scatter_kernel(const int* __restrict__ ei, int E) {
    int e = blockIdx.x * blockDim.x + threadIdx.x;
    if (e < E) {
        int dst = __ldg(ei + e);
        int src = __ldg(ei + E + e);
        int p = atomicAdd(&g_wp[dst], 1);
        g_adj[p] = src;
    }
}

// ---------------- packed-fp32 helpers (sm_103a FFMA2) ----------------
__device__ __forceinline__ unsigned long long ffma2(unsigned long long a,
                                                    unsigned long long b,
                                                    unsigned long long c) {
    unsigned long long d;
    asm("fma.rn.f32x2 %0, %1, %2, %3;" : "=l"(d) : "l"(a), "l"(b), "l"(c));
    return d;
}
__device__ __forceinline__ unsigned long long bcast2(float v) {
    unsigned long long d;
    asm("mov.b64 %0, {%1, %1};" : "=l"(d) : "f"(v));
    return d;
}

// ---------------- GEMM: g_h[N,128] = (relu?)A[N,lda->128] @ W[128,128] ----------------
// BM=64 rows/block, 256 threads, 8x4 micro-tile/thread, M packed in f32x2 lanes.
// One k-tile (K=128). Inner loop: 3 LDS + 4 mov.b64 + 16 fma.rn.f32x2 per k.
#define GEMM_SMEM ((128 * 128 + 128 * 68) * 4)

__global__ void __launch_bounds__(256, 2)
gemm_kernel(const float* __restrict__ A, int lda, int relu,
            const float* __restrict__ W, int n) {
    extern __shared__ float sm[];
    float* Ws = sm;              // [128][128] row-major (k, j)
    float* As = sm + 128 * 128;  // [128][68]  (k, m) padded: 272B rows, 16B aligned
    int tid = threadIdx.x;
    int m0 = blockIdx.x * 64;

    // load W (64KB) — coalesced float4 copy
    const float4* Wg = (const float4*)W;
    float4* Ws4 = (float4*)Ws;
#pragma unroll
    for (int i = 0; i < 16; i++) Ws4[tid + i * 256] = __ldg(Wg + tid + i * 256);

    // load A tile transposed into As[k][m], optional relu
#pragma unroll
    for (int i = 0; i < 8; i++) {
        int idx = tid + i * 256;       // 2048 float4s in the 64x128 tile
        int m = idx >> 5;
        int k4 = (idx & 31) << 2;
        int gm = m0 + m;
        float4 v = make_float4(0.f, 0.f, 0.f, 0.f);
        if (gm < n) v = __ldg((const float4*)(A + (size_t)gm * lda + k4));
        if (relu) {
            v.x = fmaxf(v.x, 0.f); v.y = fmaxf(v.y, 0.f);
            v.z = fmaxf(v.z, 0.f); v.w = fmaxf(v.w, 0.f);
        }
        As[(k4 + 0) * 68 + m] = v.x;
        As[(k4 + 1) * 68 + m] = v.y;
        As[(k4 + 2) * 68 + m] = v.z;
        As[(k4 + 3) * 68 + m] = v.w;
    }
    __syncthreads();

    int tn = tid & 31, tm = tid >> 5;   // tn: 4-col group (lane), tm: 8-row group (warp)

    // acc2[p][j]: packed pair (row 2p, row 2p+1) at column tn*4+j
    unsigned long long acc2[4][4];
#pragma unroll
    for (int p = 0; p < 4; p++)
#pragma unroll
        for (int j = 0; j < 4; j++) acc2[p][j] = 0ull;

    const float4* Wf = (const float4*)Ws;
    // shared-window byte address of As[0][tm*8]
    unsigned int aaddr = (unsigned int)__cvta_generic_to_shared(As) + tm * 32;

#pragma unroll 8
    for (int k = 0; k < 128; k++) {
        float4 w = Wf[k * 32 + tn];               // conflict-free LDS.128
        unsigned long long a01, a23, a45, a67;    // rows (0,1)(2,3)(4,5)(6,7) of micro-tile
        asm volatile("ld.shared.v2.b64 {%0, %1}, [%2];"
                     : "=l"(a01), "=l"(a23) : "r"(aaddr));        // broadcast (warp-uniform)
        asm volatile("ld.shared.v2.b64 {%0, %1}, [%2];"
                     : "=l"(a45), "=l"(a67) : "r"(aaddr + 16));
        aaddr += 272;                              // next k row (68 floats)
        unsigned long long w0 = bcast2(w.x), w1 = bcast2(w.y);
        unsigned long long w2 = bcast2(w.z), w3 = bcast2(w.w);
        acc2[0][0] = ffma2(a01, w0, acc2[0][0]);
        acc2[0][1] = ffma2(a01, w1, acc2[0][1]);
        acc2[0][2] = ffma2(a01, w2, acc2[0][2]);
        acc2[0][3] = ffma2(a01, w3, acc2[0][3]);
        acc2[1][0] = ffma2(a23, w0, acc2[1][0]);
        acc2[1][1] = ffma2(a23, w1, acc2[1][1]);
        acc2[1][2] = ffma2(a23, w2, acc2[1][2]);
        acc2[1][3] = ffma2(a23, w3, acc2[1][3]);
        acc2[2][0] = ffma2(a45, w0, acc2[2][0]);
        acc2[2][1] = ffma2(a45, w1, acc2[2][1]);
        acc2[2][2] = ffma2(a45, w2, acc2[2][2]);
        acc2[2][3] = ffma2(a45, w3, acc2[2][3]);
        acc2[3][0] = ffma2(a67, w0, acc2[3][0]);
        acc2[3][1] = ffma2(a67, w1, acc2[3][1]);
        acc2[3][2] = ffma2(a67, w2, acc2[3][2]);
        acc2[3][3] = ffma2(a67, w3, acc2[3][3]);
    }

    // epilogue: unpack pairs -> per-row float4 stores
#pragma unroll
    for (int p = 0; p < 4; p++) {
        float2 c0 = *(float2*)&acc2[p][0];
        float2 c1 = *(float2*)&acc2[p][1];
        float2 c2 = *(float2*)&acc2[p][2];
        float2 c3 = *(float2*)&acc2[p][3];
        int gm0 = m0 + tm * 8 + 2 * p;
        if (gm0 < n)
            ((float4*)g_h)[(size_t)gm0 * 32 + tn] = make_float4(c0.x, c1.x, c2.x, c3.x);
        if (gm0 + 1 < n)
            ((float4*)g_h)[(size_t)(gm0 + 1) * 32 + tn] = make_float4(c0.y, c1.y, c2.y, c3.y);
    }
}

// ---------------- aggregation: one warp per node, pull from CSR ----------------
// out[v] = dv * (dv*h[v] + sum_u dis[u]*h[u]) + b ;  out row stride 384 floats.
// 4-way unrolled: all 4 row-LDG.128s issue before any consumer so each warp keeps
// >=4 512B row-loads in flight (L2 hit ~250cyc; ~21 loads/SM in flight saturate
// the ~6300 B/cyc LTS cap; 32 resident warps x 4 >> that).
__global__ void agg_kernel(const float* __restrict__ b, float* __restrict__ out, int n) {
    int w = (blockIdx.x * blockDim.x + threadIdx.x) >> 5;
    int lane = threadIdx.x & 31;
    if (w >= n) return;
    float dv = g_dis[w];
    float4 b4 = __ldg((const float4*)b + lane);
    float4 hv = *((const float4*)(g_h + (size_t)w * DH) + lane);
    float4 acc = make_float4(dv * hv.x, dv * hv.y, dv * hv.z, dv * hv.w);
    int i = g_start[w];
    int e = i + g_cnt[w];
    int e4 = e - 3;
    for (; i < e4; i += 4) {
        int u0 = g_adj[i], u1 = g_adj[i + 1], u2 = g_adj[i + 2], u3 = g_adj[i + 3];
        const float4* p0 = (const float4*)(g_h + (size_t)u0 * DH) + lane;
        const float4* p1 = (const float4*)(g_h + (size_t)u1 * DH) + lane;
        const float4* p2 = (const float4*)(g_h + (size_t)u2 * DH) + lane;
        const float4* p3 = (const float4*)(g_h + (size_t)u3 * DH) + lane;
        float4 h0 = *p0; float4 h1 = *p1; float4 h2 = *p2; float4 h3 = *p3;
        float d0 = g_dis[u0], d1 = g_dis[u1], d2 = g_dis[u2], d3 = g_dis[u3];
        acc.x += d0 * h0.x + d1 * h1.x + d2 * h2.x + d3 * h3.x;
        acc.y += d0 * h0.y + d1 * h1.y + d2 * h2.y + d3 * h3.y;
        acc.z += d0 * h0.z + d1 * h1.z + d2 * h2.z + d3 * h3.z;
        acc.w += d0 * h0.w + d1 * h1.w + d2 * h2.w + d3 * h3.w;
    }
    for (; i < e; i++) {
        int u0 = g_adj[i];
        float d0 = g_dis[u0];
        float4 h0 = *((const float4*)(g_h + (size_t)u0 * DH) + lane);
        acc.x += d0 * h0.x;
        acc.y += d0 * h0.y;
        acc.z += d0 * h0.z;
        acc.w += d0 * h0.w;
    }
    float4 o;
    o.x = dv * acc.x + b4.x;
    o.y = dv * acc.y + b4.y;
    o.z = dv * acc.z + b4.z;
    o.w = dv * acc.w + b4.w;
    ((float4*)out)[(size_t)w * 96 + lane] = o;   // 96 float4 = 384-float row stride
}

// ---------------- launch ----------------
extern "C" void kernel_launch(void* const* d_in, const int* in_sizes, int n_in,
                              void* d_out, int out_size) {
    const float* x  = (const float*)d_in[0];
    const int*   ei = (const int*)d_in[1];
    const float* W0 = (const float*)d_in[2];
    const float* b0 = (const float*)d_in[3];
    const float* W1 = (const float*)d_in[4];
    const float* b1 = (const float*)d_in[5];
    const float* W2 = (const float*)d_in[6];
    const float* b2 = (const float*)d_in[7];
    float* out = (float*)d_out;

    int N = in_sizes[0] / DH;
    int E = in_sizes[1] / 2;

    cudaFuncSetAttribute((const void*)gemm_kernel,
                         cudaFuncAttributeMaxDynamicSharedMemorySize, GEMM_SMEM);

    int tb = 256;
    init_kernel<<<(N + tb - 1) / tb, tb>>>(N);
    hist_kernel<<<(E + tb - 1) / tb, tb>>>(ei, E);
    int nb = (N + 1023) / 1024;
    scan_kernel<<<nb, 1024>>>(N, 0);
    scan_kernel<<<1, 1024>>>(nb, 1);
    addoff_kernel<<<(N + tb - 1) / tb, tb>>>(N);
    scatter_kernel<<<(E + tb - 1) / tb, tb>>>(ei, E);

    int gemm_blocks = (N + 63) / 64;
    int agg_blocks = (N + 7) / 8;   // 8 warps/block, warp per node

    // layer 0: A = x (no relu)
    gemm_kernel<<<gemm_blocks, 256, GEMM_SMEM>>>(x, DH, 0, W0, N);
    agg_kernel<<<agg_blocks, 256>>>(b0, out + 0 * DH, N);
    // layer 1: A = relu(out[:,0,:]) with row stride 384
    gemm_kernel<<<gemm_blocks, 256, GEMM_SMEM>>>(out + 0 * DH, 3 * DH, 1, W1, N);
    agg_kernel<<<agg_blocks, 256>>>(b1, out + 1 * DH, N);
    // layer 2: A = relu(out[:,1,:])
    gemm_kernel<<<gemm_blocks, 256, GEMM_SMEM>>>(out + 1 * DH, 3 * DH, 1, W2, N);
    agg_kernel<<<agg_blocks, 256>>>(b2, out + 2 * DH, N);
}

// round 10
// speedup vs baseline: 1.0125x; 1.0125x over previous
#include <cuda_runtime.h>
#include <cuda_fp16.h>
#include <math.h>

#define NMAX 100000
#define EMAX 1600000
#define DH   128

// ---------------- static device scratch (no allocation allowed) ----------------
__device__ int   g_deg[NMAX];          // source-degree (+1 self loop) for norm
__device__ int   g_cnt[NMAX];          // dst-degree (edges only) for CSR
__device__ int   g_start[NMAX];        // CSR row start (exclusive prefix of cnt)
__device__ int   g_wp[NMAX];           // scatter write pointers
__device__ float g_dis[NMAX];          // deg^{-1/2}
__device__ int   g_adj[EMAX];          // CSR adjacency (source ids, grouped by dst)
__device__ __align__(16) __half g_hh[(size_t)NMAX * DH]; // h = A @ W, fp16 (25.6MB, L2-resident)
__device__ int   g_bsum[256];
__device__ int   g_boff[256];

// ---------------- preprocessing ----------------
__global__ void init_kernel(int n) {
    int i = blockIdx.x * blockDim.x + threadIdx.x;
    if (i < n) { g_deg[i] = 1; g_cnt[i] = 0; }   // +1 = self loop
}

__global__ void hist_kernel(const int* __restrict__ ei, int E) {
    int e = blockIdx.x * blockDim.x + threadIdx.x;
    if (e < E) {
        int dst = __ldg(ei + e);        // edge_index[0] = row = destination
        int src = __ldg(ei + E + e);    // edge_index[1] = col = source
        atomicAdd(&g_deg[src], 1);
        atomicAdd(&g_cnt[dst], 1);
    }
}

// block-wide scan, 1024 elements per block. pass=0: cnt -> start (+bsum).
// pass=1: bsum -> boff (single block).
__global__ void scan_kernel(int n, int pass) {
    __shared__ int ws[32];
    const int* in = pass ? g_bsum : g_cnt;
    int*      out = pass ? g_boff : g_start;
    int tid = threadIdx.x, lane = tid & 31, wid = tid >> 5;
    int gid = blockIdx.x * 1024 + tid;
    int v = (gid < n) ? in[gid] : 0;
    int x = v;
#pragma unroll
    for (int d = 1; d < 32; d <<= 1) {
        int y = __shfl_up_sync(0xffffffffu, x, d);
        if (lane >= d) x += y;
    }
    if (lane == 31) ws[wid] = x;
    __syncthreads();
    if (wid == 0) {
        int s = ws[lane];
#pragma unroll
        for (int d = 1; d < 32; d <<= 1) {
            int y = __shfl_up_sync(0xffffffffu, s, d);
            if (lane >= d) s += y;
        }
        ws[lane] = s;
    }
    __syncthreads();
    int woff = wid ? ws[wid - 1] : 0;
    if (gid < n) out[gid] = x + woff - v;          // exclusive
    if (pass == 0 && tid == 1023) g_bsum[blockIdx.x] = x + woff; // block total
}

// finalize CSR starts + write pointers, and compute dis = deg^{-1/2} (fused)
__global__ void addoff_kernel(int n) {
    int i = blockIdx.x * blockDim.x + threadIdx.x;
    if (i < n) {
        int s = g_start[i] + g_boff[i >> 10];
        g_start[i] = s;
        g_wp[i] = s;
        g_dis[i] = rsqrtf((float)g_deg[i]);
    }
}

__global__ void scatter_kernel(const int* __restrict__ ei, int E) {
    int e = blockIdx.x * blockDim.x + threadIdx.x;
    if (e < E) {
        int dst = __ldg(ei + e);
        int src = __ldg(ei + E + e);
        int p = atomicAdd(&g_wp[dst], 1);
        g_adj[p] = src;
    }
}

// ---------------- packed-fp32 helpers (sm_103a FFMA2) ----------------
__device__ __forceinline__ unsigned long long ffma2(unsigned long long a,
                                                    unsigned long long b,
                                                    unsigned long long c) {
    unsigned long long d;
    asm("fma.rn.f32x2 %0, %1, %2, %3;" : "=l"(d) : "l"(a), "l"(b), "l"(c));
    return d;
}
__device__ __forceinline__ unsigned long long bcast2(float v) {
    unsigned long long d;
    asm("mov.b64 %0, {%1, %1};" : "=l"(d) : "f"(v));
    return d;
}

// ---------------- GEMM: g_hh[N,128] = fp16((relu?)A[N,lda->128] @ W[128,128]) --------
// BM=64 rows/block, 256 threads, 8x4 micro-tile/thread, M packed in f32x2 lanes.
// One k-tile (K=128). Inner loop: 3 LDS + 4 mov.b64 + 16 fma.rn.f32x2 per k.
#define GEMM_SMEM ((128 * 128 + 128 * 68) * 4)

__global__ void __launch_bounds__(256, 2)
gemm_kernel(const float* __restrict__ A, int lda, int relu,
            const float* __restrict__ W, int n) {
    extern __shared__ float sm[];
    float* Ws = sm;              // [128][128] row-major (k, j)
    float* As = sm + 128 * 128;  // [128][68]  (k, m) padded: 272B rows, 16B aligned
    int tid = threadIdx.x;
    int m0 = blockIdx.x * 64;

    // load W (64KB) — coalesced float4 copy
    const float4* Wg = (const float4*)W;
    float4* Ws4 = (float4*)Ws;
#pragma unroll
    for (int i = 0; i < 16; i++) Ws4[tid + i * 256] = __ldg(Wg + tid + i * 256);

    // load A tile transposed into As[k][m], optional relu
#pragma unroll
    for (int i = 0; i < 8; i++) {
        int idx = tid + i * 256;       // 2048 float4s in the 64x128 tile
        int m = idx >> 5;
        int k4 = (idx & 31) << 2;
        int gm = m0 + m;
        float4 v = make_float4(0.f, 0.f, 0.f, 0.f);
        if (gm < n) v = __ldg((const float4*)(A + (size_t)gm * lda + k4));
        if (relu) {
            v.x = fmaxf(v.x, 0.f); v.y = fmaxf(v.y, 0.f);
            v.z = fmaxf(v.z, 0.f); v.w = fmaxf(v.w, 0.f);
        }
        As[(k4 + 0) * 68 + m] = v.x;
        As[(k4 + 1) * 68 + m] = v.y;
        As[(k4 + 2) * 68 + m] = v.z;
        As[(k4 + 3) * 68 + m] = v.w;
    }
    __syncthreads();

    int tn = tid & 31, tm = tid >> 5;   // tn: 4-col group (lane), tm: 8-row group (warp)

    // acc2[p][j]: packed pair (row 2p, row 2p+1) at column tn*4+j
    unsigned long long acc2[4][4];
#pragma unroll
    for (int p = 0; p < 4; p++)
#pragma unroll
        for (int j = 0; j < 4; j++) acc2[p][j] = 0ull;

    const float4* Wf = (const float4*)Ws;
    // shared-window byte address of As[0][tm*8]
    unsigned int aaddr = (unsigned int)__cvta_generic_to_shared(As) + tm * 32;

#pragma unroll 8
    for (int k = 0; k < 128; k++) {
        float4 w = Wf[k * 32 + tn];               // conflict-free LDS.128
        unsigned long long a01, a23, a45, a67;    // rows (0,1)(2,3)(4,5)(6,7) of micro-tile
        asm volatile("ld.shared.v2.b64 {%0, %1}, [%2];"
                     : "=l"(a01), "=l"(a23) : "r"(aaddr));        // broadcast (warp-uniform)
        asm volatile("ld.shared.v2.b64 {%0, %1}, [%2];"
                     : "=l"(a45), "=l"(a67) : "r"(aaddr + 16));
        aaddr += 272;                              // next k row (68 floats)
        unsigned long long w0 = bcast2(w.x), w1 = bcast2(w.y);
        unsigned long long w2 = bcast2(w.z), w3 = bcast2(w.w);
        acc2[0][0] = ffma2(a01, w0, acc2[0][0]);
        acc2[0][1] = ffma2(a01, w1, acc2[0][1]);
        acc2[0][2] = ffma2(a01, w2, acc2[0][2]);
        acc2[0][3] = ffma2(a01, w3, acc2[0][3]);
        acc2[1][0] = ffma2(a23, w0, acc2[1][0]);
        acc2[1][1] = ffma2(a23, w1, acc2[1][1]);
        acc2[1][2] = ffma2(a23, w2, acc2[1][2]);
        acc2[1][3] = ffma2(a23, w3, acc2[1][3]);
        acc2[2][0] = ffma2(a45, w0, acc2[2][0]);
        acc2[2][1] = ffma2(a45, w1, acc2[2][1]);
        acc2[2][2] = ffma2(a45, w2, acc2[2][2]);
        acc2[2][3] = ffma2(a45, w3, acc2[2][3]);
        acc2[3][0] = ffma2(a67, w0, acc2[3][0]);
        acc2[3][1] = ffma2(a67, w1, acc2[3][1]);
        acc2[3][2] = ffma2(a67, w2, acc2[3][2]);
        acc2[3][3] = ffma2(a67, w3, acc2[3][3]);
    }

    // epilogue: unpack pairs -> fp16, 8-byte store per row (cols tn*4..tn*4+3)
#pragma unroll
    for (int p = 0; p < 4; p++) {
        float2 c0 = *(float2*)&acc2[p][0];
        float2 c1 = *(float2*)&acc2[p][1];
        float2 c2 = *(float2*)&acc2[p][2];
        float2 c3 = *(float2*)&acc2[p][3];
        int gm0 = m0 + tm * 8 + 2 * p;
        if (gm0 < n) {
            __half2 h01 = __floats2half2_rn(c0.x, c1.x);
            __half2 h23 = __floats2half2_rn(c2.x, c3.x);
            uint2 pk = make_uint2(*(unsigned*)&h01, *(unsigned*)&h23);
            *((uint2*)(g_hh + (size_t)gm0 * DH) + tn) = pk;
        }
        if (gm0 + 1 < n) {
            __half2 h01 = __floats2half2_rn(c0.y, c1.y);
            __half2 h23 = __floats2half2_rn(c2.y, c3.y);
            uint2 pk = make_uint2(*(unsigned*)&h01, *(unsigned*)&h23);
            *((uint2*)(g_hh + (size_t)(gm0 + 1) * DH) + tn) = pk;
        }
    }
}

// load 4 fp16 columns (lane*4 .. lane*4+3) of a g_hh row as float4
__device__ __forceinline__ float4 ldh4(const __half* row, int lane) {
    uint2 r = *((const uint2*)row + lane);          // 8B per lane, 256B per warp row
    __half2 h01 = *(__half2*)&r.x;
    __half2 h23 = *(__half2*)&r.y;
    float2 f01 = __half22float2(h01);
    float2 f23 = __half22float2(h23);
    return make_float4(f01.x, f01.y, f23.x, f23.y);
}

// ---------------- aggregation: one warp per node, pull from CSR ----------------
// out[v] = dv * (dv*h[v] + sum_u dis[u]*h[u]) + b ;  out row stride 384 floats.
// fp16 gathers halve the L2 traffic (256B/row). 4-way unroll keeps >=4 rows in
// flight per warp against ~250cyc L2-hit latency.
__global__ void agg_kernel(const float* __restrict__ b, float* __restrict__ out, int n) {
    int w = (blockIdx.x * blockDim.x + threadIdx.x) >> 5;
    int lane = threadIdx.x & 31;
    if (w >= n) return;
    float dv = g_dis[w];
    float4 b4 = __ldg((const float4*)b + lane);
    float4 hv = ldh4(g_hh + (size_t)w * DH, lane);
    float4 acc = make_float4(dv * hv.x, dv * hv.y, dv * hv.z, dv * hv.w);
    int i = g_start[w];
    int e = i + g_cnt[w];
    int e4 = e - 3;
    for (; i < e4; i += 4) {
        int u0 = g_adj[i], u1 = g_adj[i + 1], u2 = g_adj[i + 2], u3 = g_adj[i + 3];
        float4 h0 = ldh4(g_hh + (size_t)u0 * DH, lane);
        float4 h1 = ldh4(g_hh + (size_t)u1 * DH, lane);
        float4 h2 = ldh4(g_hh + (size_t)u2 * DH, lane);
        float4 h3 = ldh4(g_hh + (size_t)u3 * DH, lane);
        float d0 = g_dis[u0], d1 = g_dis[u1], d2 = g_dis[u2], d3 = g_dis[u3];
        acc.x += d0 * h0.x + d1 * h1.x + d2 * h2.x + d3 * h3.x;
        acc.y += d0 * h0.y + d1 * h1.y + d2 * h2.y + d3 * h3.y;
        acc.z += d0 * h0.z + d1 * h1.z + d2 * h2.z + d3 * h3.z;
        acc.w += d0 * h0.w + d1 * h1.w + d2 * h2.w + d3 * h3.w;
    }
    for (; i < e; i++) {
        int u0 = g_adj[i];
        float d0 = g_dis[u0];
        float4 h0 = ldh4(g_hh + (size_t)u0 * DH, lane);
        acc.x += d0 * h0.x;
        acc.y += d0 * h0.y;
        acc.z += d0 * h0.z;
        acc.w += d0 * h0.w;
    }
    float4 o;
    o.x = dv * acc.x + b4.x;
    o.y = dv * acc.y + b4.y;
    o.z = dv * acc.z + b4.z;
    o.w = dv * acc.w + b4.w;
    ((float4*)out)[(size_t)w * 96 + lane] = o;   // 96 float4 = 384-float row stride
}

// ---------------- launch ----------------
extern "C" void kernel_launch(void* const* d_in, const int* in_sizes, int n_in,
                              void* d_out, int out_size) {
    const float* x  = (const float*)d_in[0];
    const int*   ei = (const int*)d_in[1];
    const float* W0 = (const float*)d_in[2];
    const float* b0 = (const float*)d_in[3];
    const float* W1 = (const float*)d_in[4];
    const float* b1 = (const float*)d_in[5];
    const float* W2 = (const float*)d_in[6];
    const float* b2 = (const float*)d_in[7];
    float* out = (float*)d_out;

    int N = in_sizes[0] / DH;
    int E = in_sizes[1] / 2;

    cudaFuncSetAttribute((const void*)gemm_kernel,
                         cudaFuncAttributeMaxDynamicSharedMemorySize, GEMM_SMEM);

    int tb = 256;
    init_kernel<<<(N + tb - 1) / tb, tb>>>(N);
    hist_kernel<<<(E + tb - 1) / tb, tb>>>(ei, E);
    int nb = (N + 1023) / 1024;
    scan_kernel<<<nb, 1024>>>(N, 0);
    scan_kernel<<<1, 1024>>>(nb, 1);
    addoff_kernel<<<(N + tb - 1) / tb, tb>>>(N);
    scatter_kernel<<<(E + tb - 1) / tb, tb>>>(ei, E);

    int gemm_blocks = (N + 63) / 64;
    int agg_blocks = (N + 7) / 8;   // 8 warps/block, warp per node

    // layer 0: A = x (no relu)
    gemm_kernel<<<gemm_blocks, 256, GEMM_SMEM>>>(x, DH, 0, W0, N);
    agg_kernel<<<agg_blocks, 256>>>(b0, out + 0 * DH, N);
    // layer 1: A = relu(out[:,0,:]) with row stride 384
    gemm_kernel<<<gemm_blocks, 256, GEMM_SMEM>>>(out + 0 * DH, 3 * DH, 1, W1, N);
    agg_kernel<<<agg_blocks, 256>>>(b1, out + 1 * DH, N);
    // layer 2: A = relu(out[:,1,:])
    gemm_kernel<<<gemm_blocks, 256, GEMM_SMEM>>>(out + 1 * DH, 3 * DH, 1, W2, N);
    agg_kernel<<<agg_blocks, 256>>>(b2, out + 2 * DH, N);
}

// round 13
// speedup vs baseline: 1.5556x; 1.5364x over previous
#include <cuda_runtime.h>
#include <cuda_fp16.h>
#include <math.h>

#define NMAX 100000
#define EMAX 1600000
#define DH   128

// ---------------- static device scratch (no allocation allowed) ----------------
__device__ int   g_deg[NMAX];          // source-degree (+1 self loop) for norm
__device__ int   g_cnt[NMAX];          // dst-degree (edges only) for CSR
__device__ int   g_start[NMAX];        // CSR row start (exclusive prefix of cnt)
__device__ int   g_wp[NMAX];           // scatter write pointers
__device__ float g_dis[NMAX];          // deg^{-1/2}
__device__ int   g_adj[EMAX];          // CSR adjacency (source ids, grouped by dst)
__device__ __align__(16) __half g_hh[(size_t)NMAX * DH]; // h = A @ W, fp16 (25.6MB, L2-resident)
__device__ int   g_bsum[256];
__device__ int   g_boff[256];

// ---------------- preprocessing ----------------
__global__ void init_kernel(int n) {
    int i = blockIdx.x * blockDim.x + threadIdx.x;
    if (i < n) { g_deg[i] = 1; g_cnt[i] = 0; }   // +1 = self loop
}

__global__ void hist_kernel(const int* __restrict__ ei, int E) {
    int e = blockIdx.x * blockDim.x + threadIdx.x;
    if (e < E) {
        int dst = __ldg(ei + e);        // edge_index[0] = row = destination
        int src = __ldg(ei + E + e);    // edge_index[1] = col = source
        atomicAdd(&g_deg[src], 1);
        atomicAdd(&g_cnt[dst], 1);
    }
}

// block-wide scan, 1024 elements per block. pass=0: cnt -> start (+bsum).
// pass=1: bsum -> boff (single block).
__global__ void scan_kernel(int n, int pass) {
    __shared__ int ws[32];
    const int* in = pass ? g_bsum : g_cnt;
    int*      out = pass ? g_boff : g_start;
    int tid = threadIdx.x, lane = tid & 31, wid = tid >> 5;
    int gid = blockIdx.x * 1024 + tid;
    int v = (gid < n) ? in[gid] : 0;
    int x = v;
#pragma unroll
    for (int d = 1; d < 32; d <<= 1) {
        int y = __shfl_up_sync(0xffffffffu, x, d);
        if (lane >= d) x += y;
    }
    if (lane == 31) ws[wid] = x;
    __syncthreads();
    if (wid == 0) {
        int s = ws[lane];
#pragma unroll
        for (int d = 1; d < 32; d <<= 1) {
            int y = __shfl_up_sync(0xffffffffu, s, d);
            if (lane >= d) s += y;
        }
        ws[lane] = s;
    }
    __syncthreads();
    int woff = wid ? ws[wid - 1] : 0;
    if (gid < n) out[gid] = x + woff - v;          // exclusive
    if (pass == 0 && tid == 1023) g_bsum[blockIdx.x] = x + woff; // block total
}

// finalize CSR starts + write pointers, and compute dis = deg^{-1/2} (fused)
__global__ void addoff_kernel(int n) {
    int i = blockIdx.x * blockDim.x + threadIdx.x;
    if (i < n) {
        int s = g_start[i] + g_boff[i >> 10];
        g_start[i] = s;
        g_wp[i] = s;
        g_dis[i] = rsqrtf((float)g_deg[i]);
    }
}

__global__ void scatter_kernel(const int* __restrict__ ei, int E) {
    int e = blockIdx.x * blockDim.x + threadIdx.x;
    if (e < E) {
        int dst = __ldg(ei + e);
        int src = __ldg(ei + E + e);
        int p = atomicAdd(&g_wp[dst], 1);
        g_adj[p] = src;
    }
}

// ---------------- packed-fp32 helpers (sm_103a FFMA2) ----------------
__device__ __forceinline__ unsigned long long ffma2(unsigned long long a,
                                                    unsigned long long b,
                                                    unsigned long long c) {
    unsigned long long d;
    asm("fma.rn.f32x2 %0, %1, %2, %3;" : "=l"(d) : "l"(a), "l"(b), "l"(c));
    return d;
}
__device__ __forceinline__ unsigned long long bcast2(float v) {
    unsigned long long d;
    asm("mov.b64 %0, {%1, %1};" : "=l"(d) : "f"(v));
    return d;
}

// ---------------- GEMM: g_hh[N,128] = fp16((relu?)A[N,lda->128] @ W[128,128]) --------
// BM=64 rows/block, 256 threads, 8x4 micro-tile/thread, M packed in f32x2 lanes.
// One k-tile (K=128). Inner loop: 3 LDS + 4 mov.b64 + 16 fma.rn.f32x2 per k.
#define GEMM_SMEM ((128 * 128 + 128 * 68) * 4)

__global__ void __launch_bounds__(256, 2)
gemm_kernel(const float* __restrict__ A, int lda, int relu,
            const float* __restrict__ W, int n) {
    extern __shared__ float sm[];
    float* Ws = sm;              // [128][128] row-major (k, j)
    float* As = sm + 128 * 128;  // [128][68]  (k, m) padded: 272B rows, 16B aligned
    int tid = threadIdx.x;
    int m0 = blockIdx.x * 64;

    // load W (64KB) — coalesced float4 copy
    const float4* Wg = (const float4*)W;
    float4* Ws4 = (float4*)Ws;
#pragma unroll
    for (int i = 0; i < 16; i++) Ws4[tid + i * 256] = __ldg(Wg + tid + i * 256);

    // load A tile transposed into As[k][m], optional relu
#pragma unroll
    for (int i = 0; i < 8; i++) {
        int idx = tid + i * 256;       // 2048 float4s in the 64x128 tile
        int m = idx >> 5;
        int k4 = (idx & 31) << 2;
        int gm = m0 + m;
        float4 v = make_float4(0.f, 0.f, 0.f, 0.f);
        if (gm < n) v = __ldg((const float4*)(A + (size_t)gm * lda + k4));
        if (relu) {
            v.x = fmaxf(v.x, 0.f); v.y = fmaxf(v.y, 0.f);
            v.z = fmaxf(v.z, 0.f); v.w = fmaxf(v.w, 0.f);
        }
        As[(k4 + 0) * 68 + m] = v.x;
        As[(k4 + 1) * 68 + m] = v.y;
        As[(k4 + 2) * 68 + m] = v.z;
        As[(k4 + 3) * 68 + m] = v.w;
    }
    __syncthreads();

    int tn = tid & 31, tm = tid >> 5;   // tn: 4-col group (lane), tm: 8-row group (warp)

    // acc2[p][j]: packed pair (row 2p, row 2p+1) at column tn*4+j
    unsigned long long acc2[4][4];
#pragma unroll
    for (int p = 0; p < 4; p++)
#pragma unroll
        for (int j = 0; j < 4; j++) acc2[p][j] = 0ull;

    const float4* Wf = (const float4*)Ws;
    // shared-window byte address of As[0][tm*8]
    unsigned int aaddr = (unsigned int)__cvta_generic_to_shared(As) + tm * 32;

#pragma unroll 8
    for (int k = 0; k < 128; k++) {
        float4 w = Wf[k * 32 + tn];               // conflict-free LDS.128
        unsigned long long a01, a23, a45, a67;    // rows (0,1)(2,3)(4,5)(6,7) of micro-tile
        asm volatile("ld.shared.v2.b64 {%0, %1}, [%2];"
                     : "=l"(a01), "=l"(a23) : "r"(aaddr));        // broadcast (warp-uniform)
        asm volatile("ld.shared.v2.b64 {%0, %1}, [%2];"
                     : "=l"(a45), "=l"(a67) : "r"(aaddr + 16));
        aaddr += 272;                              // next k row (68 floats)
        unsigned long long w0 = bcast2(w.x), w1 = bcast2(w.y);
        unsigned long long w2 = bcast2(w.z), w3 = bcast2(w.w);
        acc2[0][0] = ffma2(a01, w0, acc2[0][0]);
        acc2[0][1] = ffma2(a01, w1, acc2[0][1]);
        acc2[0][2] = ffma2(a01, w2, acc2[0][2]);
        acc2[0][3] = ffma2(a01, w3, acc2[0][3]);
        acc2[1][0] = ffma2(a23, w0, acc2[1][0]);
        acc2[1][1] = ffma2(a23, w1, acc2[1][1]);
        acc2[1][2] = ffma2(a23, w2, acc2[1][2]);
        acc2[1][3] = ffma2(a23, w3, acc2[1][3]);
        acc2[2][0] = ffma2(a45, w0, acc2[2][0]);
        acc2[2][1] = ffma2(a45, w1, acc2[2][1]);
        acc2[2][2] = ffma2(a45, w2, acc2[2][2]);
        acc2[2][3] = ffma2(a45, w3, acc2[2][3]);
        acc2[3][0] = ffma2(a67, w0, acc2[3][0]);
        acc2[3][1] = ffma2(a67, w1, acc2[3][1]);
        acc2[3][2] = ffma2(a67, w2, acc2[3][2]);
        acc2[3][3] = ffma2(a67, w3, acc2[3][3]);
    }

    // epilogue: unpack pairs -> fp16, 8-byte store per row (cols tn*4..tn*4+3)
#pragma unroll
    for (int p = 0; p < 4; p++) {
        float2 c0 = *(float2*)&acc2[p][0];
        float2 c1 = *(float2*)&acc2[p][1];
        float2 c2 = *(float2*)&acc2[p][2];
        float2 c3 = *(float2*)&acc2[p][3];
        int gm0 = m0 + tm * 8 + 2 * p;
        if (gm0 < n) {
            __half2 h01 = __floats2half2_rn(c0.x, c1.x);
            __half2 h23 = __floats2half2_rn(c2.x, c3.x);
            uint2 pk = make_uint2(*(unsigned*)&h01, *(unsigned*)&h23);
            *((uint2*)(g_hh + (size_t)gm0 * DH) + tn) = pk;
        }
        if (gm0 + 1 < n) {
            __half2 h01 = __floats2half2_rn(c0.y, c1.y);
            __half2 h23 = __floats2half2_rn(c2.y, c3.y);
            uint2 pk = make_uint2(*(unsigned*)&h01, *(unsigned*)&h23);
            *((uint2*)(g_hh + (size_t)(gm0 + 1) * DH) + tn) = pk;
        }
    }
}

// load 4 fp16 columns (lane*4 .. lane*4+3) of a g_hh row as float4
__device__ __forceinline__ float4 ldh4(const __half* row, int lane) {
    uint2 r = *((const uint2*)row + lane);          // 8B per lane, 256B per warp row
    __half2 h01 = *(__half2*)&r.x;
    __half2 h23 = *(__half2*)&r.y;
    float2 f01 = __half22float2(h01);
    float2 f23 = __half22float2(h23);
    return make_float4(f01.x, f01.y, f23.x, f23.y);
}

// ---------------- aggregation: one warp per node, pull from CSR ----------------
// out[v] = dv * (dv*h[v] + sum_u dis[u]*h[u]) + b ;  out row stride 384 floats.
// 8-way unrolled: 8 independent row-loads in flight per warp to cover L2-hit
// latency (~250cyc). Tests the latency-bound hypothesis (fp16 byte-halving was
// ~neutral, so agg is not L2-BW-bound).
__global__ void agg_kernel(const float* __restrict__ b, float* __restrict__ out, int n) {
    int w = (blockIdx.x * blockDim.x + threadIdx.x) >> 5;
    int lane = threadIdx.x & 31;
    if (w >= n) return;
    float dv = g_dis[w];
    float4 b4 = __ldg((const float4*)b + lane);
    float4 hv = ldh4(g_hh + (size_t)w * DH, lane);
    float4 acc = make_float4(dv * hv.x, dv * hv.y, dv * hv.z, dv * hv.w);
    int i = g_start[w];
    int e = i + g_cnt[w];
    int e8 = e - 7;
    for (; i < e8; i += 8) {
        int u0 = g_adj[i],     u1 = g_adj[i + 1], u2 = g_adj[i + 2], u3 = g_adj[i + 3];
        int u4 = g_adj[i + 4], u5 = g_adj[i + 5], u6 = g_adj[i + 6], u7 = g_adj[i + 7];
        float4 h0 = ldh4(g_hh + (size_t)u0 * DH, lane);
        float4 h1 = ldh4(g_hh + (size_t)u1 * DH, lane);
        float4 h2 = ldh4(g_hh + (size_t)u2 * DH, lane);
        float4 h3 = ldh4(g_hh + (size_t)u3 * DH, lane);
        float4 h4 = ldh4(g_hh + (size_t)u4 * DH, lane);
        float4 h5 = ldh4(g_hh + (size_t)u5 * DH, lane);
        float4 h6 = ldh4(g_hh + (size_t)u6 * DH, lane);
        float4 h7 = ldh4(g_hh + (size_t)u7 * DH, lane);
        float d0 = g_dis[u0], d1 = g_dis[u1], d2 = g_dis[u2], d3 = g_dis[u3];
        float d4 = g_dis[u4], d5 = g_dis[u5], d6 = g_dis[u6], d7 = g_dis[u7];
        acc.x += d0 * h0.x + d1 * h1.x + d2 * h2.x + d3 * h3.x
               + d4 * h4.x + d5 * h5.x + d6 * h6.x + d7 * h7.x;
        acc.y += d0 * h0.y + d1 * h1.y + d2 * h2.y + d3 * h3.y
               + d4 * h4.y + d5 * h5.y + d6 * h6.y + d7 * h7.y;
        acc.z += d0 * h0.z + d1 * h1.z + d2 * h2.z + d3 * h3.z
               + d4 * h4.z + d5 * h5.z + d6 * h6.z + d7 * h7.z;
        acc.w += d0 * h0.w + d1 * h1.w + d2 * h2.w + d3 * h3.w
               + d4 * h4.w + d5 * h5.w + d6 * h6.w + d7 * h7.w;
    }
    for (; i < e; i++) {
        int u0 = g_adj[i];
        float d0 = g_dis[u0];
        float4 h0 = ldh4(g_hh + (size_t)u0 * DH, lane);
        acc.x += d0 * h0.x;
        acc.y += d0 * h0.y;
        acc.z += d0 * h0.z;
        acc.w += d0 * h0.w;
    }
    float4 o;
    o.x = dv * acc.x + b4.x;
    o.y = dv * acc.y + b4.y;
    o.z = dv * acc.z + b4.z;
    o.w = dv * acc.w + b4.w;
    ((float4*)out)[(size_t)w * 96 + lane] = o;   // 96 float4 = 384-float row stride
}

// ---------------- launch ----------------
extern "C" void kernel_launch(void* const* d_in, const int* in_sizes, int n_in,
                              void* d_out, int out_size) {
    const float* x  = (const float*)d_in[0];
    const int*   ei = (const int*)d_in[1];
    const float* W0 = (const float*)d_in[2];
    const float* b0 = (const float*)d_in[3];
    const float* W1 = (const float*)d_in[4];
    const float* b1 = (const float*)d_in[5];
    const float* W2 = (const float*)d_in[6];
    const float* b2 = (const float*)d_in[7];
    float* out = (float*)d_out;

    int N = in_sizes[0] / DH;
    int E = in_sizes[1] / 2;

    cudaFuncSetAttribute((const void*)gemm_kernel,
                         cudaFuncAttributeMaxDynamicSharedMemorySize, GEMM_SMEM);

    int tb = 256;
    int gemm_blocks = (N + 63) / 64;
    int agg_blocks = (N + 7) / 8;   // 8 warps/block, warp per node
    int nb = (N + 1023) / 1024;

    init_kernel<<<(N + tb - 1) / tb, tb>>>(N);
    hist_kernel<<<(E + tb - 1) / tb, tb>>>(ei, E);
    scan_kernel<<<nb, 1024>>>(N, 0);
    // layer-0 GEMM moved here (depends only on x/W0) so it lands in the
    // harness's fixed ncu capture slot (stream launch index 3) -> attribution.
    gemm_kernel<<<gemm_blocks, 256, GEMM_SMEM>>>(x, DH, 0, W0, N);
    scan_kernel<<<1, 1024>>>(nb, 1);
    addoff_kernel<<<(N + tb - 1) / tb, tb>>>(N);
    scatter_kernel<<<(E + tb - 1) / tb, tb>>>(ei, E);

    // layer 0 aggregation
    agg_kernel<<<agg_blocks, 256>>>(b0, out + 0 * DH, N);
    // layer 1: A = relu(out[:,0,:]) with row stride 384
    gemm_kernel<<<gemm_blocks, 256, GEMM_SMEM>>>(out + 0 * DH, 3 * DH, 1, W1, N);
    agg_kernel<<<agg_blocks, 256>>>(b1, out + 1 * DH, N);
    // layer 2: A = relu(out[:,1,:])
    gemm_kernel<<<gemm_blocks, 256, GEMM_SMEM>>>(out + 1 * DH, 3 * DH, 1, W2, N);
    agg_kernel<<<agg_blocks, 256>>>(b2, out + 2 * DH, N);
}